// round 7
// baseline (speedup 1.0000x reference)
#include <cuda_runtime.h>
#include <cuda_bf16.h>

// FuzzyLayer: out[b,s,d*I+i] = exp(-(x[b,s,i]-mu[d,i])^2 / sigma[d,i])
// B=16, S=2048, I=256, D=8.  256 MB write + 32 MB read -> HBM-write-bound.
//
// R6 -> R7: write-path experiment. All R3-R6 structural variants sit in a
// 45-49us band (DRAM 61-68%) -> test whether per-warp STG streams are the
// drain bottleneck. Output now staged in SMEM and written with TMA bulk
// stores (cp.async.bulk.global.shared::cta), 16 KB contiguous descriptors,
// double-buffered; SM pipelines never issue STG at all.
// Kept from R4 (best): short blocks (grid 4096, 8 rows each -> desync),
// params in regs (poly exp2((a*x+b)*x+e)), single x fill + barrier,
// float4/LDS traffic, __launch_bounds__(512,4).

static constexpr int ROWS  = 8;             // x rows per block
static constexpr int SUB   = 2;             // rows per bulk store (16 KB)
static constexpr int NSTEP = ROWS / SUB;    // 4
static constexpr int BS    = 16 * 2048;     // 32768 rows

__device__ __forceinline__ float ex2_approx(float t) {
    float r;
    asm("ex2.approx.ftz.f32 %0, %1;" : "=f"(r) : "f"(t));
    return r;
}

__global__ void __launch_bounds__(512, 4)
fuzzy_kernel(const float4* __restrict__ x4,
             const float4* __restrict__ fp4,
             float4* __restrict__ out4)
{
    __shared__ float4 sx[ROWS * 64];           // 8 KB  : x tile
    __shared__ float4 so[2][SUB * 512];        // 32 KB : output staging (2 bufs)

    const int tid = threadIdx.x;
    const int i4  = tid & 63;                  // float4 group within I
    const int d   = tid >> 6;                  // fuzzy degree

    // fuzzy_params (2048,2) row-major: fp[2j]=mu_j, fp[2j+1]=sigma_j, j=d*256+i.
    const float4 p0 = fp4[d * 128 + i4 * 2];
    const float4 p1 = fp4[d * 128 + i4 * 2 + 1];

    const float L2E = 1.4426950408889634f;
    // exponent(x) = rs*(x-mu)^2 = (a*x + b)*x + e
    const float a0 = -L2E / p0.y, b0 = -2.f * a0 * p0.x, e0 = a0 * p0.x * p0.x;
    const float a1 = -L2E / p0.w, b1 = -2.f * a1 * p0.z, e1 = a1 * p0.z * p0.z;
    const float a2 = -L2E / p1.y, b2 = -2.f * a2 * p1.x, e2 = a2 * p1.x * p1.x;
    const float a3 = -L2E / p1.w, b3 = -2.f * a3 * p1.z, e3 = a3 * p1.z * p1.z;

    const int bs0 = blockIdx.x * ROWS;

    // Fill x tile: 512 float4 = 1 per thread.
    sx[tid] = x4[(size_t)bs0 * 64 + tid];
    __syncthreads();

    const unsigned so_base = (unsigned)__cvta_generic_to_shared(&so[0][0]);
    float4* gdst = out4 + (size_t)bs0 * 512;

#pragma unroll
    for (int s = 0; s < NSTEP; ++s) {
        const int buf = s & 1;

        if (s >= 2) {
            // Buffer reuse: wait until at most 1 bulk-store group still
            // reading SMEM, then release all threads to overwrite it.
            if (tid == 0)
                asm volatile("cp.async.bulk.wait_group.read 1;" ::: "memory");
            __syncthreads();
        }

        // Compute rows 2s, 2s+1 into so[buf] (layout == gmem layout).
#pragma unroll
        for (int lr = 0; lr < SUB; ++lr) {
            const float4 xv = sx[(s * SUB + lr) * 64 + i4];
            float4 o;
            o.x = ex2_approx(fmaf(fmaf(a0, xv.x, b0), xv.x, e0));
            o.y = ex2_approx(fmaf(fmaf(a1, xv.y, b1), xv.y, e1));
            o.z = ex2_approx(fmaf(fmaf(a2, xv.z, b2), xv.z, e2));
            o.w = ex2_approx(fmaf(fmaf(a3, xv.w, b3), xv.w, e3));
            so[buf][lr * 512 + tid] = o;
        }

        // Make generic-proxy SMEM writes visible to the async proxy,
        // then one thread issues the 16 KB bulk store.
        asm volatile("fence.proxy.async.shared::cta;" ::: "memory");
        __syncthreads();
        if (tid == 0) {
            const unsigned saddr = so_base + (unsigned)buf * (SUB * 512 * 16);
            asm volatile(
                "cp.async.bulk.global.shared::cta.bulk_group [%0], [%1], %2;"
                :: "l"(gdst + s * SUB * 512), "r"(saddr), "r"(SUB * 512 * 16)
                : "memory");
            asm volatile("cp.async.bulk.commit_group;" ::: "memory");
        }
    }

    // SMEM must stay alive until the TMA engine has read it.
    if (tid == 0)
        asm volatile("cp.async.bulk.wait_group.read 0;" ::: "memory");
    __syncthreads();
}

extern "C" void kernel_launch(void* const* d_in, const int* in_sizes, int n_in,
                              void* d_out, int out_size)
{
    const float4* x4  = (const float4*)d_in[0];   // x: (16,2048,256) f32
    const float4* fp4 = (const float4*)d_in[1];   // fuzzy_params: (2048,2) f32
    float4* out4      = (float4*)d_out;           // (16,2048,2048) f32

    fuzzy_kernel<<<BS / ROWS, 512>>>(x4, fp4, out4);   // 4096 blocks
}

// round 8
// speedup vs baseline: 1.0767x; 1.0767x over previous
#include <cuda_runtime.h>
#include <cuda_bf16.h>

// FuzzyLayer: out[b,s,d*I+i] = exp(-(x[b,s,i]-mu[d,i])^2 / sigma[d,i])
// B=16, S=2048, I=256, D=8.  268 MB write + 33 MB read -> HBM-write-bound.
//
// R7 -> R8: TMA store path was neutral-to-worse (drain is path-independent);
// every variant with extra barriers (R5/R6/R7) lost to R4. So: exact R4
// structure, with the tile halved (ROWS 32 -> 16, grid 1024 -> 2048) for
// finer cross-CTA desync (shorter fill windows, more independent blocks
// staggering their fill phases against other CTAs' store bursts).
// Kept: single cooperative SMEM fill + ONE barrier, thread owns fixed
// output column group (poly coeffs in regs: exp2((a*x+b)*x+e)), all 8 'd'
// groups co-resident, float4 traffic, __stcs streaming stores,
// __launch_bounds__(512,4).

static constexpr int BS    = 16 * 2048;     // 32768 rows
static constexpr int ROWS  = 16;            // rows per block (16 KB smem)

__device__ __forceinline__ float ex2_approx(float t) {
    float r;
    asm("ex2.approx.ftz.f32 %0, %1;" : "=f"(r) : "f"(t));
    return r;
}

__global__ void __launch_bounds__(512, 4)
fuzzy_kernel(const float4* __restrict__ x4,
             const float4* __restrict__ fp4,
             float4* __restrict__ out4)
{
    __shared__ float4 sx[ROWS * 64];         // 16 KB: ROWS rows of x (256 f32)

    const int tid = threadIdx.x;
    const int i4  = tid & 63;                // float4 group within I
    const int d   = tid >> 6;                // fuzzy degree

    // fuzzy_params (2048,2) row-major: fp[2j]=mu_j, fp[2j+1]=sigma_j, j=d*256+i.
    const float4 p0 = fp4[d * 128 + i4 * 2];
    const float4 p1 = fp4[d * 128 + i4 * 2 + 1];

    const float L2E = 1.4426950408889634f;
    // exponent(x) = rs*(x-mu)^2 = (a*x + b)*x + e
    const float a0 = -L2E / p0.y, b0 = -2.f * a0 * p0.x, e0 = a0 * p0.x * p0.x;
    const float a1 = -L2E / p0.w, b1 = -2.f * a1 * p0.z, e1 = a1 * p0.z * p0.z;
    const float a2 = -L2E / p1.y, b2 = -2.f * a2 * p1.x, e2 = a2 * p1.x * p1.x;
    const float a3 = -L2E / p1.w, b3 = -2.f * a3 * p1.z, e3 = a3 * p1.z * p1.z;

    const int bs0 = blockIdx.x * ROWS;

    // Cooperative fill: ROWS*64 = 1024 float4 / 512 threads = 2 per thread.
    {
        const float4* __restrict__ src = x4 + (size_t)bs0 * 64;
        sx[tid]       = src[tid];
        sx[tid + 512] = src[tid + 512];
    }
    __syncthreads();

    float4* __restrict__ oout = out4 + (size_t)bs0 * 512 + tid;

#pragma unroll 4
    for (int r = 0; r < ROWS; ++r) {
        const float4 xv = sx[r * 64 + i4];

        float4 o;
        o.x = ex2_approx(fmaf(fmaf(a0, xv.x, b0), xv.x, e0));
        o.y = ex2_approx(fmaf(fmaf(a1, xv.y, b1), xv.y, e1));
        o.z = ex2_approx(fmaf(fmaf(a2, xv.z, b2), xv.z, e2));
        o.w = ex2_approx(fmaf(fmaf(a3, xv.w, b3), xv.w, e3));

        __stcs(oout + r * 512, o);
    }
}

extern "C" void kernel_launch(void* const* d_in, const int* in_sizes, int n_in,
                              void* d_out, int out_size)
{
    const float4* x4  = (const float4*)d_in[0];   // x: (16,2048,256) f32
    const float4* fp4 = (const float4*)d_in[1];   // fuzzy_params: (2048,2) f32
    float4* out4      = (float4*)d_out;           // (16,2048,2048) f32

    fuzzy_kernel<<<BS / ROWS, 512>>>(x4, fp4, out4);   // 2048 blocks
}